// round 13
// baseline (speedup 1.0000x reference)
#include <cuda_runtime.h>
#include <cuda_bf16.h>
#include <cuda_fp16.h>
#include <cstdint>

#define D_ 6
#define N_ 32768
#define K_ 16
#define DIN_ 64
#define DOUT_ 64

typedef unsigned long long u64;

// Interleaved ping-pong state, 16B per (row, dim-pair):
//   word0 (u64): c as f32x2
//   word1 (u64): low u32 = h as f16x2, high u32 = G(=0.5*h@Uf) as f16x2
// Row 0 = zero row for masked children: .bss zero, never written.
__device__ u64 g_st[2][(N_ + 1) * 64];
// Precomputed Wx for all depths, f16x2 per dim-pair: [6*N][128], blocks f|i|u|o
__device__ uint32_t g_Wxh[(size_t)D_ * N_ * 128];
// Pre-swizzled f16 weight planes (node kernel): UA[6144] | UF[2048]  (u32 words)
__device__ uint32_t g_Wpl[8192];
// Pre-swizzled split-bf16 W_w planes (wx kernel): [256n][64k] hi | lo
__device__ uint32_t g_Wxb[16384];
// software grid barrier
__device__ unsigned g_cnt;
__device__ unsigned g_gen;

#define HALF2 0x3F0000003F000000ULL   // {0.5f, 0.5f}

__device__ __forceinline__ u64 pk2(float lo, float hi) {
    u64 r; asm("mov.b64 %0, {%1,%2};" : "=l"(r) : "f"(lo), "f"(hi)); return r;
}
__device__ __forceinline__ void upk2(u64 v, float& lo, float& hi) {
    asm("mov.b64 {%0,%1}, %2;" : "=f"(lo), "=f"(hi) : "l"(v));
}
__device__ __forceinline__ u64 fma2_(u64 a, u64 b, u64 c) {
    u64 d; asm("fma.rn.f32x2 %0, %1, %2, %3;" : "=l"(d) : "l"(a), "l"(b), "l"(c)); return d;
}
__device__ __forceinline__ u64 add2_(u64 a, u64 b) {
    u64 d; asm("add.rn.f32x2 %0, %1, %2;" : "=l"(d) : "l"(a), "l"(b)); return d;
}
__device__ __forceinline__ u64 mul2_(u64 a, u64 b) {
    u64 d; asm("mul.rn.f32x2 %0, %1, %2;" : "=l"(d) : "l"(a), "l"(b)); return d;
}
__device__ __forceinline__ float tanha(float x) {
    float y; asm("tanh.approx.f32 %0, %1;" : "=f"(y) : "f"(x)); return y;
}
__device__ __forceinline__ u64 sig2h(u64 argHalf) {   // sigmoid(2*arg), arg pre-halved
    float a, b; upk2(argHalf, a, b);
    return fma2_(pk2(tanha(a), tanha(b)), HALF2, HALF2);
}
__device__ __forceinline__ u64 tanh2(u64 v) {
    float a, b; upk2(v, a, b);
    return pk2(tanha(a), tanha(b));
}
__device__ __forceinline__ uint32_t smem_u32(const void* p) {
    uint32_t a;
    asm("{ .reg .u64 t; cvta.to.shared.u64 t, %1; cvt.u32.u64 %0, t; }" : "=r"(a) : "l"(p));
    return a;
}
__device__ __forceinline__ uint32_t bf2pk(float lo, float hi) {
    uint32_t r;
    asm("cvt.rn.bf16x2.f32 %0, %1, %2;" : "=r"(r) : "f"(hi), "f"(lo));
    return r;
}
__device__ __forceinline__ uint32_t h2pk(float lo, float hi) {
    __half2 h = __float22half2_rn(make_float2(lo, hi));
    return *reinterpret_cast<uint32_t*>(&h);
}
__device__ __forceinline__ u64 h2up(uint32_t v) {   // f16x2 -> f32x2 (u64)
    __half2 h = *reinterpret_cast<__half2*>(&v);
    float2 f = __half22float2(h);
    return pk2(f.x, f.y);
}
#define SW128(off) ((off) ^ (((off) >> 3) & 0x70))

__device__ __forceinline__ void ldm_x4(uint32_t* r, uint32_t addr) {
    asm volatile("ldmatrix.sync.aligned.m8n8.x4.shared.b16 {%0,%1,%2,%3}, [%4];"
                 : "=r"(r[0]), "=r"(r[1]), "=r"(r[2]), "=r"(r[3]) : "r"(addr));
}
__device__ __forceinline__ void mma16816(float* c, const uint32_t* a,
                                         uint32_t b0, uint32_t b1) {
    asm volatile(
        "mma.sync.aligned.m16n8k16.row.col.f32.bf16.bf16.f32 "
        "{%0,%1,%2,%3}, {%4,%5,%6,%7}, {%8,%9}, {%0,%1,%2,%3};"
        : "+f"(c[0]), "+f"(c[1]), "+f"(c[2]), "+f"(c[3])
        : "r"(a[0]), "r"(a[1]), "r"(a[2]), "r"(a[3]), "r"(b0), "r"(b1));
}
__device__ __forceinline__ void mma16816h(float* c, const uint32_t* a,
                                          uint32_t b0, uint32_t b1) {
    asm volatile(
        "mma.sync.aligned.m16n8k16.row.col.f32.f16.f16.f32 "
        "{%0,%1,%2,%3}, {%4,%5,%6,%7}, {%8,%9}, {%0,%1,%2,%3};"
        : "+f"(c[0]), "+f"(c[1]), "+f"(c[2]), "+f"(c[3])
        : "r"(a[0]), "r"(a[1]), "r"(a[2]), "r"(a[3]), "r"(b0), "r"(b1));
}

__device__ __forceinline__ void split_store(float x, float y, uint32_t* hip,
                                            uint32_t* lop) {
    uint32_t hi = bf2pk(x, y);
    float rl = x - __uint_as_float(hi << 16);
    float rr = y - __uint_as_float(hi & 0xFFFF0000u);
    *hip = hi;
    *lop = bf2pk(rl, rr);
}

// ============ prep: build static weight planes + reset barrier ====================
// g_Wpl: UA f16 [192n][64k] (6144 u32) | UF f16 x0.5 [64n][64k] (2048 u32)
// g_Wxb: split-bf16 W_w [256n][64k]: hi[8192) | lo[8192)
__global__ void prep_kernel(const float* __restrict__ Uf,
                            const float* __restrict__ Uiuo,
                            const float* __restrict__ Ww) {
    if (blockIdx.x == 0 && threadIdx.x == 0) { g_cnt = 0u; g_gen = 0u; }
    int idx0 = blockIdx.x * 256 + threadIdx.x;
    for (int idx = idx0; idx < 16384; idx += 2048) {
        if (idx < 6144) {                 // U_iuo f16 plane
            int n = idx >> 5, kp = idx & 31;
            uint32_t off = SW128((uint32_t)(n * 128 + kp * 4)) >> 2;
            g_Wpl[off] = h2pk(Uiuo[(2 * kp) * 192 + n], Uiuo[(2 * kp + 1) * 192 + n]);
        } else if (idx < 8192) {          // U_f f16 plane (x0.5)
            int i = idx - 6144;
            int n = i >> 5, kp = i & 31;
            uint32_t off = SW128((uint32_t)(n * 128 + kp * 4)) >> 2;
            g_Wpl[6144 + off] = h2pk(0.5f * Uf[(2 * kp) * 64 + n],
                                     0.5f * Uf[(2 * kp + 1) * 64 + n]);
        } else {                          // W_w split-bf16 planes
            int i = idx - 8192;
            int n = i >> 5, kp = i & 31;
            float x = Ww[(2 * kp) * 256 + n], y = Ww[(2 * kp + 1) * 256 + n];
            uint32_t off = SW128((uint32_t)(n * 128 + kp * 4)) >> 2;
            split_store(x, y, g_Wxb + off, g_Wxb + 8192 + off);
        }
    }
}

// ======================= wx GEMM: A staged once, both column halves ===============
#define WXA_HI 0
#define WXA_LO 16384
#define WXB_HI 32768
#define WXB_LO 49152
#define WX_SMEM 65536

__global__ __launch_bounds__(256) void wx_mma_kernel(const int* __restrict__ labels,
                                                     const float* __restrict__ E,
                                                     const float* __restrict__ Wb) {
    extern __shared__ char smc[];
    __shared__ int lab_s[128];
    uint32_t sb = smem_u32(smc);
    const int t = threadIdx.x;
    const int lane = t & 31, w = t >> 5;
    const int rowbase = blockIdx.x * 128;

    if (t < 128) lab_s[t] = labels[rowbase + t];
    __syncthreads();

#pragma unroll
    for (int i = 0; i < 8; i++) {
        int linear = i * 256 + t;
        int r = linear >> 4, f = linear & 15;
        float4 v = __ldg(reinterpret_cast<const float4*>(
                             E + (size_t)lab_s[r] * DIN_) + f);
        uint32_t h01 = bf2pk(v.x, v.y), h23 = bf2pk(v.z, v.w);
        float l0 = v.x - __uint_as_float(h01 << 16);
        float l1 = v.y - __uint_as_float(h01 & 0xFFFF0000u);
        float l2 = v.z - __uint_as_float(h23 << 16);
        float l3 = v.w - __uint_as_float(h23 & 0xFFFF0000u);
        uint32_t q01 = bf2pk(l0, l1), q23 = bf2pk(l2, l3);
        uint32_t off = SW128((uint32_t)(r * 128 + f * 8));
        *reinterpret_cast<u64*>(smc + WXA_HI + off) = ((u64)h23 << 32) | h01;
        *reinterpret_cast<u64*>(smc + WXA_LO + off) = ((u64)q23 << 32) | q01;
    }

    const int mbase = 32 * (w & 3);
    const int nbase = 64 * (w >> 2);
    const int lrow = ((lane >> 3) & 1) * 8 + (lane & 7);
    const int lkb  = (lane >> 4) * 16;
    const int gid = lane >> 2, qc = lane & 3;

#pragma unroll
    for (int h = 0; h < 2; h++) {
        __syncthreads();
        {
            const uint4* src_h = reinterpret_cast<const uint4*>(g_Wxb) + h * 1024;
            const uint4* src_l = reinterpret_cast<const uint4*>(g_Wxb + 8192) + h * 1024;
            uint4* dst_h = reinterpret_cast<uint4*>(smc + WXB_HI);
            uint4* dst_l = reinterpret_cast<uint4*>(smc + WXB_LO);
#pragma unroll
            for (int i = 0; i < 4; i++) {
                dst_h[i * 256 + t] = __ldg(src_h + i * 256 + t);
                dst_l[i * 256 + t] = __ldg(src_l + i * 256 + t);
            }
        }
        __syncthreads();

        float acc[2][8][4];
#pragma unroll
        for (int mt = 0; mt < 2; mt++)
#pragma unroll
            for (int nt = 0; nt < 8; nt++)
#pragma unroll
                for (int e = 0; e < 4; e++) acc[mt][nt][e] = 0.f;

#pragma unroll
        for (int pass = 0; pass < 3; pass++) {
            const uint32_t Ab = sb + ((pass == 1) ? WXA_LO : WXA_HI);
            const uint32_t Bb = sb + ((pass == 2) ? WXB_LO : WXB_HI);
#pragma unroll
            for (int kc = 0; kc < 4; kc++) {
                const int koff = kc * 32 + lkb;
                uint32_t a[2][4];
#pragma unroll
                for (int mt = 0; mt < 2; mt++) {
                    int r = mbase + 16 * mt + lrow;
                    ldm_x4(a[mt], Ab + SW128((uint32_t)(r * 128 + koff)));
                }
#pragma unroll
                for (int tp = 0; tp < 4; tp++) {
                    int n = nbase + tp * 16 + lrow;
                    uint32_t b[4];
                    ldm_x4(b, Bb + SW128((uint32_t)(n * 128 + koff)));
                    mma16816(acc[0][2 * tp],     a[0], b[0], b[2]);
                    mma16816(acc[0][2 * tp + 1], a[0], b[1], b[3]);
                    mma16816(acc[1][2 * tp],     a[1], b[0], b[2]);
                    mma16816(acc[1][2 * tp + 1], a[1], b[1], b[3]);
                }
            }
        }

#pragma unroll
        for (int mt = 0; mt < 2; mt++) {
#pragma unroll
            for (int nt = 0; nt < 8; nt++) {
                int col = h * 128 + nbase + nt * 8 + 2 * qc;
                float2 bia = __ldg(reinterpret_cast<const float2*>(Wb + col));
                int row0 = rowbase + mbase + 16 * mt + gid;
                g_Wxh[(size_t)row0 * 128 + (col >> 1)] =
                    h2pk(acc[mt][nt][0] + bia.x, acc[mt][nt][1] + bia.y);
                g_Wxh[(size_t)(row0 + 8) * 128 + (col >> 1)] =
                    h2pk(acc[mt][nt][2] + bia.x, acc[mt][nt][3] + bia.y);
            }
        }
    }
}

// ========== fused node kernel: persistent, f16 single-pass, 3 CTAs/SM ============
#define UA_F 0
#define UF_F 24576
#define AS_F 32768
#define BFOF 40960
#define NODE_SMEM 49408   // UA 24K + UF 8K + AS 8K + BF 64x33 u32
#define NODE_GRID 444     // 3 CTAs/SM x 148 SMs
#define NTILES 512        // N_/64; CTAs 0..67 take a second tile (444+bid)

__global__ __launch_bounds__(256, 3) void node_all_kernel(const int* __restrict__ child_idx,
                                                          float* __restrict__ out) {
    extern __shared__ char smc[];
    const uint32_t sb = smem_u32(smc);
    const int tid = threadIdx.x, lane = tid & 31, w = tid >> 5;

    const unsigned gen0 = *((volatile unsigned*)&g_gen);   // 0 (prep resets)

    // stage f16 weight planes ONCE per CTA (persists across all depths)
    for (int i = tid; i < 2048; i += 256)
        reinterpret_cast<uint4*>(smc)[i] = __ldg(reinterpret_cast<const uint4*>(g_Wpl) + i);
    __syncthreads();

    uint32_t* BF32 = reinterpret_cast<uint32_t*>(smc + BFOF);
    const unsigned FULL = 0xffffffffu;
    const int g = lane >> 2, q = lane & 3;
    const int mrow = 16 * (w & 3), cg = w >> 2;
    const int lrow = ((lane >> 3) & 1) * 8 + (lane & 7);
    const int lkb  = (lane >> 4) * 16;
    const int ntiles = (blockIdx.x < NTILES - NODE_GRID) ? 2 : 1;

    for (int depth = 0; depth < D_; depth++) {
        const int rb = depth & 1;
        const u64* __restrict__ sp = g_st[rb];
        u64* __restrict__ sn = g_st[rb ^ 1];
        const size_t dN = (size_t)depth * N_;
        const bool last = (depth == D_ - 1);

        for (int ts = 0; ts < ntiles; ts++) {
            if (ts) __syncthreads();   // AS/BF reuse hazard across tiles
            const int nb = (blockIdx.x + ts * NODE_GRID) * 64;

            // ================= phase 1: gather (LDG.128 per child) =================
            if (depth != 0) {
#pragma unroll
                for (int iter = 0; iter < 2; iter++) {
                    const int n0 = nb + 32 * iter + 4 * w;
                    int ci0 = child_idx[(dN + n0) * K_ + lane];
                    int ci1 = child_idx[(dN + n0) * K_ + 32 + lane];
                    u64 wfh[4], hs[4] = {0, 0, 0, 0}, bfa[4] = {0, 0, 0, 0};
#pragma unroll
                    for (int q4 = 0; q4 < 4; q4++)
                        wfh[q4] = mul2_(h2up(__ldg(g_Wxh + (dN + n0 + q4) * 128 + lane)),
                                        HALF2);
#pragma unroll 4
                    for (int k = 0; k < K_; k++) {
#pragma unroll
                        for (int q4 = 0; q4 < 4; q4++) {
                            int sl = q4 * 16 + k;
                            int c = (sl < 32) ? __shfl_sync(FULL, ci0, sl)
                                              : __shfl_sync(FULL, ci1, sl - 32);
                            ulonglong2 s = __ldg(reinterpret_cast<const ulonglong2*>(
                                                     sp + 2 * (c * 32 + lane)));
                            hs[q4] = add2_(hs[q4], h2up((uint32_t)s.y));
                            bfa[q4] = fma2_(s.x,
                                            sig2h(add2_(wfh[q4],
                                                        h2up((uint32_t)(s.y >> 32)))),
                                            bfa[q4]);
                        }
                    }
#pragma unroll
                    for (int q4 = 0; q4 < 4; q4++) {
                        int r = 32 * iter + 4 * w + q4;
                        float xl, xh; upk2(hs[q4], xl, xh);
                        uint32_t o = SW128((uint32_t)(r * 128 + 4 * lane));
                        *reinterpret_cast<uint32_t*>(smc + AS_F + o) = h2pk(xl, xh);
                        float bl, bh; upk2(bfa[q4], bl, bh);
                        BF32[r * 33 + lane] = h2pk(bl, bh);
                    }
                }
                __syncthreads();
            }

            // ================= phase 2: iuo = hs @ U_iuo (f16 single pass) =========
            float acc[3][4][4];
#pragma unroll
            for (int b = 0; b < 3; b++)
#pragma unroll
                for (int j4 = 0; j4 < 4; j4++)
#pragma unroll
                    for (int e = 0; e < 4; e++) acc[b][j4][e] = 0.f;

            if (depth != 0) {
#pragma unroll
                for (int kc = 0; kc < 4; kc++) {
                    const int koff = kc * 32 + lkb;
                    uint32_t a[4];
                    ldm_x4(a, sb + AS_F + SW128((uint32_t)((mrow + lrow) * 128 + koff)));
#pragma unroll
                    for (int b = 0; b < 3; b++)
#pragma unroll
                        for (int tp = 0; tp < 2; tp++) {
                            int nrow = b * 64 + cg * 32 + tp * 16 + lrow;
                            uint32_t bb[4];
                            ldm_x4(bb, sb + UA_F + SW128((uint32_t)(nrow * 128 + koff)));
                            mma16816h(acc[b][2 * tp],     a, bb[0], bb[2]);
                            mma16816h(acc[b][2 * tp + 1], a, bb[1], bb[3]);
                        }
                }
            }

            // ================= phase 3: gates =================
            u64 nhv[4][2];
#pragma unroll
            for (int j4 = 0; j4 < 4; j4++) {
                const int dp = 16 * cg + 4 * j4 + q;
#pragma unroll
                for (int rh = 0; rh < 2; rh++) {
                    const int r = mrow + 8 * rh + g;
                    const uint32_t* wq = g_Wxh + (dN + nb + r) * 128;
                    u64 ai = pk2(acc[0][j4][2 * rh], acc[0][j4][2 * rh + 1]);
                    u64 au = pk2(acc[1][j4][2 * rh], acc[1][j4][2 * rh + 1]);
                    u64 ao = pk2(acc[2][j4][2 * rh], acc[2][j4][2 * rh + 1]);
                    u64 ig = sig2h(mul2_(add2_(ai, h2up(__ldg(wq + 32 + dp))), HALF2));
                    u64 ug = tanh2(add2_(au, h2up(__ldg(wq + 64 + dp))));
                    u64 og = sig2h(mul2_(add2_(ao, h2up(__ldg(wq + 96 + dp))), HALF2));
                    u64 bfv = (depth != 0) ? h2up(BF32[r * 33 + dp]) : 0ULL;
                    u64 ncv = fma2_(ig, ug, bfv);
                    u64 nh = mul2_(og, tanh2(ncv));
                    nhv[j4][rh] = nh;
                    if (last) {
                        reinterpret_cast<u64*>(out)[(size_t)(nb + r) * 32 + dp] = nh;
                    } else {
                        sn[2 * ((size_t)(nb + r + 1) * 32 + dp)] = ncv;   // c word
                    }
                }
            }

            if (!last) {
                // ============ phase 4: stage new_h, G = 0.5*(new_h @ U_f) ============
                __syncthreads();
#pragma unroll
                for (int j4 = 0; j4 < 4; j4++) {
                    const int dp = 16 * cg + 4 * j4 + q;
#pragma unroll
                    for (int rh = 0; rh < 2; rh++) {
                        const int r = mrow + 8 * rh + g;
                        float xl, xh; upk2(nhv[j4][rh], xl, xh);
                        uint32_t o = SW128((uint32_t)(r * 128 + 4 * dp));
                        *reinterpret_cast<uint32_t*>(smc + AS_F + o) = h2pk(xl, xh);
                    }
                }
                __syncthreads();

                float ga[4][4];
#pragma unroll
                for (int t2 = 0; t2 < 4; t2++)
#pragma unroll
                    for (int e = 0; e < 4; e++) ga[t2][e] = 0.f;

#pragma unroll
                for (int kc = 0; kc < 4; kc++) {
                    const int koff = kc * 32 + lkb;
                    uint32_t a[4];
                    ldm_x4(a, sb + AS_F + SW128((uint32_t)((mrow + lrow) * 128 + koff)));
#pragma unroll
                    for (int tp = 0; tp < 2; tp++) {
                        int nrow = cg * 32 + tp * 16 + lrow;
                        uint32_t bb[4];
                        ldm_x4(bb, sb + UF_F + SW128((uint32_t)(nrow * 128 + koff)));
                        mma16816h(ga[2 * tp],     a, bb[0], bb[2]);
                        mma16816h(ga[2 * tp + 1], a, bb[1], bb[3]);
                    }
                }
#pragma unroll
                for (int tg = 0; tg < 4; tg++) {
                    const int dp = 16 * cg + 4 * tg + q;
#pragma unroll
                    for (int rh = 0; rh < 2; rh++) {
                        const int r = mrow + 8 * rh + g;
                        float xl, xh; upk2(nhv[tg][rh], xl, xh);
                        uint32_t hu = h2pk(xl, xh);
                        uint32_t gu = h2pk(ga[tg][2 * rh], ga[tg][2 * rh + 1]);
                        sn[2 * ((size_t)(nb + r + 1) * 32 + dp) + 1] =
                            ((u64)gu << 32) | hu;                       // hG word
                    }
                }
            }
        }

        // ================= grid barrier between depths =================
        if (!last) {
            __syncthreads();
            if (tid == 0) {
                __threadfence();
                unsigned a = atomicAdd(&g_cnt, 1u);
                unsigned target = gen0 + (unsigned)depth + 1u;
                if ((a % NODE_GRID) == NODE_GRID - 1) {
                    atomicAdd(&g_gen, 1u);
                } else {
                    while (*((volatile unsigned*)&g_gen) < target) {}
                }
                __threadfence();
            }
            __syncthreads();
        }
    }
}

extern "C" void kernel_launch(void* const* d_in, const int* in_sizes, int n_in,
                              void* d_out, int out_size) {
    const int*   labels    = (const int*)d_in[0];
    const int*   child_idx = (const int*)d_in[1];
    const float* E         = (const float*)d_in[2];
    const float* Ww        = (const float*)d_in[3];
    const float* Wb        = (const float*)d_in[4];
    const float* Uf        = (const float*)d_in[5];
    const float* Uiuo      = (const float*)d_in[6];
    float*       out       = (float*)d_out;

    cudaFuncSetAttribute(node_all_kernel, cudaFuncAttributeMaxDynamicSharedMemorySize,
                         NODE_SMEM);
    cudaFuncSetAttribute(wx_mma_kernel, cudaFuncAttributeMaxDynamicSharedMemorySize,
                         WX_SMEM);

    prep_kernel<<<8, 256>>>(Uf, Uiuo, Ww);
    wx_mma_kernel<<<(D_ * N_) / 128, 256, WX_SMEM>>>(labels, E, Wb);
    node_all_kernel<<<NODE_GRID, 256, NODE_SMEM>>>(child_idx, out);
}

// round 14
// speedup vs baseline: 1.1322x; 1.1322x over previous
#include <cuda_runtime.h>
#include <cuda_bf16.h>
#include <cuda_fp16.h>
#include <cstdint>

#define D_ 6
#define N_ 32768
#define K_ 16
#define DIN_ 64
#define DOUT_ 64

typedef unsigned long long u64;

// Interleaved ping-pong state, 16B per (row, dim-pair):
//   word0 (u64): c as f32x2
//   word1 (u64): low u32 = h as f16x2, high u32 = G(=0.5*h@Uf) as f16x2
// Row 0 = zero row for masked children: .bss zero, never written.
__device__ u64 g_st[2][(N_ + 1) * 64];
// Precomputed Wx for all depths, f16x2 per dim-pair: [6*N][128], blocks f|i|u|o
__device__ uint32_t g_Wxh[(size_t)D_ * N_ * 128];
// Pre-swizzled f16 weight planes (node kernel): UA[6144] | UF[2048]  (u32 words)
__device__ uint32_t g_Wpl[8192];
// Pre-swizzled split-bf16 W_w planes (wx kernel): [256n][64k] hi | lo
__device__ uint32_t g_Wxb[16384];
// software grid barrier
__device__ unsigned g_cnt;
__device__ unsigned g_gen;

#define HALF2 0x3F0000003F000000ULL   // {0.5f, 0.5f}

__device__ __forceinline__ u64 pk2(float lo, float hi) {
    u64 r; asm("mov.b64 %0, {%1,%2};" : "=l"(r) : "f"(lo), "f"(hi)); return r;
}
__device__ __forceinline__ void upk2(u64 v, float& lo, float& hi) {
    asm("mov.b64 {%0,%1}, %2;" : "=f"(lo), "=f"(hi) : "l"(v));
}
__device__ __forceinline__ u64 fma2_(u64 a, u64 b, u64 c) {
    u64 d; asm("fma.rn.f32x2 %0, %1, %2, %3;" : "=l"(d) : "l"(a), "l"(b), "l"(c)); return d;
}
__device__ __forceinline__ u64 add2_(u64 a, u64 b) {
    u64 d; asm("add.rn.f32x2 %0, %1, %2;" : "=l"(d) : "l"(a), "l"(b)); return d;
}
__device__ __forceinline__ u64 mul2_(u64 a, u64 b) {
    u64 d; asm("mul.rn.f32x2 %0, %1, %2;" : "=l"(d) : "l"(a), "l"(b)); return d;
}
__device__ __forceinline__ float tanha(float x) {
    float y; asm("tanh.approx.f32 %0, %1;" : "=f"(y) : "f"(x)); return y;
}
__device__ __forceinline__ u64 sig2h(u64 argHalf) {   // sigmoid(2*arg), arg pre-halved
    float a, b; upk2(argHalf, a, b);
    return fma2_(pk2(tanha(a), tanha(b)), HALF2, HALF2);
}
__device__ __forceinline__ u64 tanh2(u64 v) {
    float a, b; upk2(v, a, b);
    return pk2(tanha(a), tanha(b));
}
__device__ __forceinline__ uint32_t smem_u32(const void* p) {
    uint32_t a;
    asm("{ .reg .u64 t; cvta.to.shared.u64 t, %1; cvt.u32.u64 %0, t; }" : "=r"(a) : "l"(p));
    return a;
}
__device__ __forceinline__ uint32_t bf2pk(float lo, float hi) {
    uint32_t r;
    asm("cvt.rn.bf16x2.f32 %0, %1, %2;" : "=r"(r) : "f"(hi), "f"(lo));
    return r;
}
__device__ __forceinline__ uint32_t h2pk(float lo, float hi) {
    __half2 h = __float22half2_rn(make_float2(lo, hi));
    return *reinterpret_cast<uint32_t*>(&h);
}
__device__ __forceinline__ u64 h2up(uint32_t v) {   // f16x2 -> f32x2 (u64)
    __half2 h = *reinterpret_cast<__half2*>(&v);
    float2 f = __half22float2(h);
    return pk2(f.x, f.y);
}
#define SW128(off) ((off) ^ (((off) >> 3) & 0x70))

__device__ __forceinline__ void ldm_x4(uint32_t* r, uint32_t addr) {
    asm volatile("ldmatrix.sync.aligned.m8n8.x4.shared.b16 {%0,%1,%2,%3}, [%4];"
                 : "=r"(r[0]), "=r"(r[1]), "=r"(r[2]), "=r"(r[3]) : "r"(addr));
}
__device__ __forceinline__ void mma16816(float* c, const uint32_t* a,
                                         uint32_t b0, uint32_t b1) {
    asm volatile(
        "mma.sync.aligned.m16n8k16.row.col.f32.bf16.bf16.f32 "
        "{%0,%1,%2,%3}, {%4,%5,%6,%7}, {%8,%9}, {%0,%1,%2,%3};"
        : "+f"(c[0]), "+f"(c[1]), "+f"(c[2]), "+f"(c[3])
        : "r"(a[0]), "r"(a[1]), "r"(a[2]), "r"(a[3]), "r"(b0), "r"(b1));
}
__device__ __forceinline__ void mma16816h(float* c, const uint32_t* a,
                                          uint32_t b0, uint32_t b1) {
    asm volatile(
        "mma.sync.aligned.m16n8k16.row.col.f32.f16.f16.f32 "
        "{%0,%1,%2,%3}, {%4,%5,%6,%7}, {%8,%9}, {%0,%1,%2,%3};"
        : "+f"(c[0]), "+f"(c[1]), "+f"(c[2]), "+f"(c[3])
        : "r"(a[0]), "r"(a[1]), "r"(a[2]), "r"(a[3]), "r"(b0), "r"(b1));
}

__device__ __forceinline__ void split_store(float x, float y, uint32_t* hip,
                                            uint32_t* lop) {
    uint32_t hi = bf2pk(x, y);
    float rl = x - __uint_as_float(hi << 16);
    float rr = y - __uint_as_float(hi & 0xFFFF0000u);
    *hip = hi;
    *lop = bf2pk(rl, rr);
}

// ============ prep: build static weight planes + reset barrier ====================
// g_Wpl: UA f16 [192n][64k] (6144 u32) | UF f16 x0.5 [64n][64k] (2048 u32)
// g_Wxb: split-bf16 W_w [256n][64k]: hi[8192) | lo[8192)
__global__ void prep_kernel(const float* __restrict__ Uf,
                            const float* __restrict__ Uiuo,
                            const float* __restrict__ Ww) {
    if (blockIdx.x == 0 && threadIdx.x == 0) { g_cnt = 0u; g_gen = 0u; }
    int idx0 = blockIdx.x * 256 + threadIdx.x;
    for (int idx = idx0; idx < 16384; idx += 2048) {
        if (idx < 6144) {                 // U_iuo f16 plane
            int n = idx >> 5, kp = idx & 31;
            uint32_t off = SW128((uint32_t)(n * 128 + kp * 4)) >> 2;
            g_Wpl[off] = h2pk(Uiuo[(2 * kp) * 192 + n], Uiuo[(2 * kp + 1) * 192 + n]);
        } else if (idx < 8192) {          // U_f f16 plane (x0.5)
            int i = idx - 6144;
            int n = i >> 5, kp = i & 31;
            uint32_t off = SW128((uint32_t)(n * 128 + kp * 4)) >> 2;
            g_Wpl[6144 + off] = h2pk(0.5f * Uf[(2 * kp) * 64 + n],
                                     0.5f * Uf[(2 * kp + 1) * 64 + n]);
        } else {                          // W_w split-bf16 planes
            int i = idx - 8192;
            int n = i >> 5, kp = i & 31;
            float x = Ww[(2 * kp) * 256 + n], y = Ww[(2 * kp + 1) * 256 + n];
            uint32_t off = SW128((uint32_t)(n * 128 + kp * 4)) >> 2;
            split_store(x, y, g_Wxb + off, g_Wxb + 8192 + off);
        }
    }
}

// ======================= wx GEMM: A staged once, both column halves ===============
#define WXA_HI 0
#define WXA_LO 16384
#define WXB_HI 32768
#define WXB_LO 49152
#define WX_SMEM 65536

__global__ __launch_bounds__(256) void wx_mma_kernel(const int* __restrict__ labels,
                                                     const float* __restrict__ E,
                                                     const float* __restrict__ Wb) {
    extern __shared__ char smc[];
    __shared__ int lab_s[128];
    uint32_t sb = smem_u32(smc);
    const int t = threadIdx.x;
    const int lane = t & 31, w = t >> 5;
    const int rowbase = blockIdx.x * 128;

    if (t < 128) lab_s[t] = labels[rowbase + t];
    __syncthreads();

#pragma unroll
    for (int i = 0; i < 8; i++) {
        int linear = i * 256 + t;
        int r = linear >> 4, f = linear & 15;
        float4 v = __ldg(reinterpret_cast<const float4*>(
                             E + (size_t)lab_s[r] * DIN_) + f);
        uint32_t h01 = bf2pk(v.x, v.y), h23 = bf2pk(v.z, v.w);
        float l0 = v.x - __uint_as_float(h01 << 16);
        float l1 = v.y - __uint_as_float(h01 & 0xFFFF0000u);
        float l2 = v.z - __uint_as_float(h23 << 16);
        float l3 = v.w - __uint_as_float(h23 & 0xFFFF0000u);
        uint32_t q01 = bf2pk(l0, l1), q23 = bf2pk(l2, l3);
        uint32_t off = SW128((uint32_t)(r * 128 + f * 8));
        *reinterpret_cast<u64*>(smc + WXA_HI + off) = ((u64)h23 << 32) | h01;
        *reinterpret_cast<u64*>(smc + WXA_LO + off) = ((u64)q23 << 32) | q01;
    }

    const int mbase = 32 * (w & 3);
    const int nbase = 64 * (w >> 2);
    const int lrow = ((lane >> 3) & 1) * 8 + (lane & 7);
    const int lkb  = (lane >> 4) * 16;
    const int gid = lane >> 2, qc = lane & 3;

#pragma unroll
    for (int h = 0; h < 2; h++) {
        __syncthreads();
        {
            const uint4* src_h = reinterpret_cast<const uint4*>(g_Wxb) + h * 1024;
            const uint4* src_l = reinterpret_cast<const uint4*>(g_Wxb + 8192) + h * 1024;
            uint4* dst_h = reinterpret_cast<uint4*>(smc + WXB_HI);
            uint4* dst_l = reinterpret_cast<uint4*>(smc + WXB_LO);
#pragma unroll
            for (int i = 0; i < 4; i++) {
                dst_h[i * 256 + t] = __ldg(src_h + i * 256 + t);
                dst_l[i * 256 + t] = __ldg(src_l + i * 256 + t);
            }
        }
        __syncthreads();

        float acc[2][8][4];
#pragma unroll
        for (int mt = 0; mt < 2; mt++)
#pragma unroll
            for (int nt = 0; nt < 8; nt++)
#pragma unroll
                for (int e = 0; e < 4; e++) acc[mt][nt][e] = 0.f;

#pragma unroll
        for (int pass = 0; pass < 3; pass++) {
            const uint32_t Ab = sb + ((pass == 1) ? WXA_LO : WXA_HI);
            const uint32_t Bb = sb + ((pass == 2) ? WXB_LO : WXB_HI);
#pragma unroll
            for (int kc = 0; kc < 4; kc++) {
                const int koff = kc * 32 + lkb;
                uint32_t a[2][4];
#pragma unroll
                for (int mt = 0; mt < 2; mt++) {
                    int r = mbase + 16 * mt + lrow;
                    ldm_x4(a[mt], Ab + SW128((uint32_t)(r * 128 + koff)));
                }
#pragma unroll
                for (int tp = 0; tp < 4; tp++) {
                    int n = nbase + tp * 16 + lrow;
                    uint32_t b[4];
                    ldm_x4(b, Bb + SW128((uint32_t)(n * 128 + koff)));
                    mma16816(acc[0][2 * tp],     a[0], b[0], b[2]);
                    mma16816(acc[0][2 * tp + 1], a[0], b[1], b[3]);
                    mma16816(acc[1][2 * tp],     a[1], b[0], b[2]);
                    mma16816(acc[1][2 * tp + 1], a[1], b[1], b[3]);
                }
            }
        }

#pragma unroll
        for (int mt = 0; mt < 2; mt++) {
#pragma unroll
            for (int nt = 0; nt < 8; nt++) {
                int col = h * 128 + nbase + nt * 8 + 2 * qc;
                float2 bia = __ldg(reinterpret_cast<const float2*>(Wb + col));
                int row0 = rowbase + mbase + 16 * mt + gid;
                g_Wxh[(size_t)row0 * 128 + (col >> 1)] =
                    h2pk(acc[mt][nt][0] + bia.x, acc[mt][nt][1] + bia.y);
                g_Wxh[(size_t)(row0 + 8) * 128 + (col >> 1)] =
                    h2pk(acc[mt][nt][2] + bia.x, acc[mt][nt][3] + bia.y);
            }
        }
    }
}

// ========== fused node kernel: persistent, f16 single-pass matvecs ===============
// Round-12 schedule (256 CTAs x exactly 2 tiles, launch_bounds(256,2)) restored.
#define UA_F 0
#define UF_F 24576
#define AS_F 32768
#define BFOF 40960
#define NODE_SMEM 49408   // UA 24K + UF 8K + AS 8K + BF 64x33 u32
#define NODE_GRID 256

__global__ __launch_bounds__(256, 2) void node_all_kernel(const int* __restrict__ child_idx,
                                                          float* __restrict__ out) {
    extern __shared__ char smc[];
    const uint32_t sb = smem_u32(smc);
    const int tid = threadIdx.x, lane = tid & 31, w = tid >> 5;

    const unsigned gen0 = *((volatile unsigned*)&g_gen);   // 0 (prep resets)

    // stage f16 weight planes ONCE per CTA (persists across all depths)
    for (int i = tid; i < 2048; i += 256)
        reinterpret_cast<uint4*>(smc)[i] = __ldg(reinterpret_cast<const uint4*>(g_Wpl) + i);
    __syncthreads();

    uint32_t* BF32 = reinterpret_cast<uint32_t*>(smc + BFOF);
    const unsigned FULL = 0xffffffffu;
    const int g = lane >> 2, q = lane & 3;
    const int mrow = 16 * (w & 3), cg = w >> 2;
    const int lrow = ((lane >> 3) & 1) * 8 + (lane & 7);
    const int lkb  = (lane >> 4) * 16;

    for (int depth = 0; depth < D_; depth++) {
        const int rb = depth & 1;
        const u64* __restrict__ sp = g_st[rb];
        u64* __restrict__ sn = g_st[rb ^ 1];
        const size_t dN = (size_t)depth * N_;
        const bool last = (depth == D_ - 1);

        for (int ts = 0; ts < 2; ts++) {
            if (ts) __syncthreads();   // AS/BF reuse hazard across tiles
            const int nb = (blockIdx.x * 2 + ts) * 64;

            // ================= phase 1: gather (LDG.128 per child) =================
            if (depth != 0) {
#pragma unroll
                for (int iter = 0; iter < 2; iter++) {
                    const int n0 = nb + 32 * iter + 4 * w;
                    int ci0 = child_idx[(dN + n0) * K_ + lane];
                    int ci1 = child_idx[(dN + n0) * K_ + 32 + lane];
                    u64 wfh[4], hs[4] = {0, 0, 0, 0}, bfa[4] = {0, 0, 0, 0};
#pragma unroll
                    for (int q4 = 0; q4 < 4; q4++)
                        wfh[q4] = mul2_(h2up(__ldg(g_Wxh + (dN + n0 + q4) * 128 + lane)),
                                        HALF2);
#pragma unroll 4
                    for (int k = 0; k < K_; k++) {
#pragma unroll
                        for (int q4 = 0; q4 < 4; q4++) {
                            int sl = q4 * 16 + k;
                            int c = (sl < 32) ? __shfl_sync(FULL, ci0, sl)
                                              : __shfl_sync(FULL, ci1, sl - 32);
                            ulonglong2 s = __ldg(reinterpret_cast<const ulonglong2*>(
                                                     sp + 2 * (c * 32 + lane)));
                            hs[q4] = add2_(hs[q4], h2up((uint32_t)s.y));
                            bfa[q4] = fma2_(s.x,
                                            sig2h(add2_(wfh[q4],
                                                        h2up((uint32_t)(s.y >> 32)))),
                                            bfa[q4]);
                        }
                    }
#pragma unroll
                    for (int q4 = 0; q4 < 4; q4++) {
                        int r = 32 * iter + 4 * w + q4;
                        float xl, xh; upk2(hs[q4], xl, xh);
                        uint32_t o = SW128((uint32_t)(r * 128 + 4 * lane));
                        *reinterpret_cast<uint32_t*>(smc + AS_F + o) = h2pk(xl, xh);
                        float bl, bh; upk2(bfa[q4], bl, bh);
                        BF32[r * 33 + lane] = h2pk(bl, bh);
                    }
                }
                __syncthreads();
            }

            // ================= phase 2: iuo = hs @ U_iuo (f16 single pass) =========
            float acc[3][4][4];
#pragma unroll
            for (int b = 0; b < 3; b++)
#pragma unroll
                for (int j4 = 0; j4 < 4; j4++)
#pragma unroll
                    for (int e = 0; e < 4; e++) acc[b][j4][e] = 0.f;

            if (depth != 0) {
#pragma unroll
                for (int kc = 0; kc < 4; kc++) {
                    const int koff = kc * 32 + lkb;
                    uint32_t a[4];
                    ldm_x4(a, sb + AS_F + SW128((uint32_t)((mrow + lrow) * 128 + koff)));
#pragma unroll
                    for (int b = 0; b < 3; b++)
#pragma unroll
                        for (int tp = 0; tp < 2; tp++) {
                            int nrow = b * 64 + cg * 32 + tp * 16 + lrow;
                            uint32_t bb[4];
                            ldm_x4(bb, sb + UA_F + SW128((uint32_t)(nrow * 128 + koff)));
                            mma16816h(acc[b][2 * tp],     a, bb[0], bb[2]);
                            mma16816h(acc[b][2 * tp + 1], a, bb[1], bb[3]);
                        }
                }
            }

            // ================= phase 3: gates =================
            u64 nhv[4][2];
#pragma unroll
            for (int j4 = 0; j4 < 4; j4++) {
                const int dp = 16 * cg + 4 * j4 + q;
#pragma unroll
                for (int rh = 0; rh < 2; rh++) {
                    const int r = mrow + 8 * rh + g;
                    const uint32_t* wq = g_Wxh + (dN + nb + r) * 128;
                    u64 ai = pk2(acc[0][j4][2 * rh], acc[0][j4][2 * rh + 1]);
                    u64 au = pk2(acc[1][j4][2 * rh], acc[1][j4][2 * rh + 1]);
                    u64 ao = pk2(acc[2][j4][2 * rh], acc[2][j4][2 * rh + 1]);
                    u64 ig = sig2h(mul2_(add2_(ai, h2up(__ldg(wq + 32 + dp))), HALF2));
                    u64 ug = tanh2(add2_(au, h2up(__ldg(wq + 64 + dp))));
                    u64 og = sig2h(mul2_(add2_(ao, h2up(__ldg(wq + 96 + dp))), HALF2));
                    u64 bfv = (depth != 0) ? h2up(BF32[r * 33 + dp]) : 0ULL;
                    u64 ncv = fma2_(ig, ug, bfv);
                    u64 nh = mul2_(og, tanh2(ncv));
                    nhv[j4][rh] = nh;
                    if (last) {
                        reinterpret_cast<u64*>(out)[(size_t)(nb + r) * 32 + dp] = nh;
                    } else {
                        sn[2 * ((size_t)(nb + r + 1) * 32 + dp)] = ncv;   // c word
                    }
                }
            }

            if (!last) {
                // ============ phase 4: stage new_h, G = 0.5*(new_h @ U_f) ============
                __syncthreads();
#pragma unroll
                for (int j4 = 0; j4 < 4; j4++) {
                    const int dp = 16 * cg + 4 * j4 + q;
#pragma unroll
                    for (int rh = 0; rh < 2; rh++) {
                        const int r = mrow + 8 * rh + g;
                        float xl, xh; upk2(nhv[j4][rh], xl, xh);
                        uint32_t o = SW128((uint32_t)(r * 128 + 4 * dp));
                        *reinterpret_cast<uint32_t*>(smc + AS_F + o) = h2pk(xl, xh);
                    }
                }
                __syncthreads();

                float ga[4][4];
#pragma unroll
                for (int t2 = 0; t2 < 4; t2++)
#pragma unroll
                    for (int e = 0; e < 4; e++) ga[t2][e] = 0.f;

#pragma unroll
                for (int kc = 0; kc < 4; kc++) {
                    const int koff = kc * 32 + lkb;
                    uint32_t a[4];
                    ldm_x4(a, sb + AS_F + SW128((uint32_t)((mrow + lrow) * 128 + koff)));
#pragma unroll
                    for (int tp = 0; tp < 2; tp++) {
                        int nrow = cg * 32 + tp * 16 + lrow;
                        uint32_t bb[4];
                        ldm_x4(bb, sb + UF_F + SW128((uint32_t)(nrow * 128 + koff)));
                        mma16816h(ga[2 * tp],     a, bb[0], bb[2]);
                        mma16816h(ga[2 * tp + 1], a, bb[1], bb[3]);
                    }
                }
#pragma unroll
                for (int tg = 0; tg < 4; tg++) {
                    const int dp = 16 * cg + 4 * tg + q;
#pragma unroll
                    for (int rh = 0; rh < 2; rh++) {
                        const int r = mrow + 8 * rh + g;
                        float xl, xh; upk2(nhv[tg][rh], xl, xh);
                        uint32_t hu = h2pk(xl, xh);
                        uint32_t gu = h2pk(ga[tg][2 * rh], ga[tg][2 * rh + 1]);
                        sn[2 * ((size_t)(nb + r + 1) * 32 + dp) + 1] =
                            ((u64)gu << 32) | hu;                       // hG word
                    }
                }
            }
        }

        // ================= grid barrier between depths =================
        if (!last) {
            __syncthreads();
            if (tid == 0) {
                __threadfence();
                unsigned a = atomicAdd(&g_cnt, 1u);
                unsigned target = gen0 + (unsigned)depth + 1u;
                if ((a % NODE_GRID) == NODE_GRID - 1) {
                    atomicAdd(&g_gen, 1u);
                } else {
                    while (*((volatile unsigned*)&g_gen) < target) {}
                }
                __threadfence();
            }
            __syncthreads();
        }
    }
}

extern "C" void kernel_launch(void* const* d_in, const int* in_sizes, int n_in,
                              void* d_out, int out_size) {
    const int*   labels    = (const int*)d_in[0];
    const int*   child_idx = (const int*)d_in[1];
    const float* E         = (const float*)d_in[2];
    const float* Ww        = (const float*)d_in[3];
    const float* Wb        = (const float*)d_in[4];
    const float* Uf        = (const float*)d_in[5];
    const float* Uiuo      = (const float*)d_in[6];
    float*       out       = (float*)d_out;

    cudaFuncSetAttribute(node_all_kernel, cudaFuncAttributeMaxDynamicSharedMemorySize,
                         NODE_SMEM);
    cudaFuncSetAttribute(wx_mma_kernel, cudaFuncAttributeMaxDynamicSharedMemorySize,
                         WX_SMEM);

    prep_kernel<<<8, 256>>>(Uf, Uiuo, Ww);
    wx_mma_kernel<<<(D_ * N_) / 128, 256, WX_SMEM>>>(labels, E, Wb);
    node_all_kernel<<<NODE_GRID, 256, NODE_SMEM>>>(child_idx, out);
}

// round 15
// speedup vs baseline: 1.7912x; 1.5821x over previous
#include <cuda_runtime.h>
#include <cuda_bf16.h>
#include <cuda_fp16.h>
#include <cstdint>

#define D_ 6
#define N_ 32768
#define K_ 16
#define DIN_ 64
#define DOUT_ 64

typedef unsigned long long u64;

// Interleaved ping-pong state, 16B per (row, dim-pair):
//   word0 (u64): c as f32x2
//   word1 (u64): low u32 = h as f16x2, high u32 = G(=0.5*h@Uf) as f16x2
// Row 0 = zero row for masked children: .bss zero, never written.
__device__ u64 g_st[2][(N_ + 1) * 64];
// Pre-swizzled f16 weight planes: UA[6144] | UF[2048] | WW[8192]  (u32 words)
//   UA: U_iuo [192n][64k]; UF: 0.5*U_f [64n][64k]; WW: W_w [256n][64k] (f|i|u|o)
__device__ uint32_t g_Wpl[16384];
// software grid barrier
__device__ unsigned g_cnt;
__device__ unsigned g_gen;

#define HALF2 0x3F0000003F000000ULL   // {0.5f, 0.5f}

__device__ __forceinline__ u64 pk2(float lo, float hi) {
    u64 r; asm("mov.b64 %0, {%1,%2};" : "=l"(r) : "f"(lo), "f"(hi)); return r;
}
__device__ __forceinline__ void upk2(u64 v, float& lo, float& hi) {
    asm("mov.b64 {%0,%1}, %2;" : "=f"(lo), "=f"(hi) : "l"(v));
}
__device__ __forceinline__ u64 fma2_(u64 a, u64 b, u64 c) {
    u64 d; asm("fma.rn.f32x2 %0, %1, %2, %3;" : "=l"(d) : "l"(a), "l"(b), "l"(c)); return d;
}
__device__ __forceinline__ u64 add2_(u64 a, u64 b) {
    u64 d; asm("add.rn.f32x2 %0, %1, %2;" : "=l"(d) : "l"(a), "l"(b)); return d;
}
__device__ __forceinline__ u64 mul2_(u64 a, u64 b) {
    u64 d; asm("mul.rn.f32x2 %0, %1, %2;" : "=l"(d) : "l"(a), "l"(b)); return d;
}
__device__ __forceinline__ float tanha(float x) {
    float y; asm("tanh.approx.f32 %0, %1;" : "=f"(y) : "f"(x)); return y;
}
__device__ __forceinline__ u64 sig2h(u64 argHalf) {   // sigmoid(2*arg), arg pre-halved
    float a, b; upk2(argHalf, a, b);
    return fma2_(pk2(tanha(a), tanha(b)), HALF2, HALF2);
}
__device__ __forceinline__ u64 tanh2(u64 v) {
    float a, b; upk2(v, a, b);
    return pk2(tanha(a), tanha(b));
}
__device__ __forceinline__ uint32_t smem_u32(const void* p) {
    uint32_t a;
    asm("{ .reg .u64 t; cvta.to.shared.u64 t, %1; cvt.u32.u64 %0, t; }" : "=r"(a) : "l"(p));
    return a;
}
__device__ __forceinline__ uint32_t h2pk(float lo, float hi) {
    __half2 h = __float22half2_rn(make_float2(lo, hi));
    return *reinterpret_cast<uint32_t*>(&h);
}
__device__ __forceinline__ u64 h2up(uint32_t v) {   // f16x2 -> f32x2 (u64)
    __half2 h = *reinterpret_cast<__half2*>(&v);
    float2 f = __half22float2(h);
    return pk2(f.x, f.y);
}
#define SW128(off) ((off) ^ (((off) >> 3) & 0x70))

__device__ __forceinline__ void ldm_x4(uint32_t* r, uint32_t addr) {
    asm volatile("ldmatrix.sync.aligned.m8n8.x4.shared.b16 {%0,%1,%2,%3}, [%4];"
                 : "=r"(r[0]), "=r"(r[1]), "=r"(r[2]), "=r"(r[3]) : "r"(addr));
}
__device__ __forceinline__ void mma16816h(float* c, const uint32_t* a,
                                          uint32_t b0, uint32_t b1) {
    asm volatile(
        "mma.sync.aligned.m16n8k16.row.col.f32.f16.f16.f32 "
        "{%0,%1,%2,%3}, {%4,%5,%6,%7}, {%8,%9}, {%0,%1,%2,%3};"
        : "+f"(c[0]), "+f"(c[1]), "+f"(c[2]), "+f"(c[3])
        : "r"(a[0]), "r"(a[1]), "r"(a[2]), "r"(a[3]), "r"(b0), "r"(b1));
}

// ============ prep: build static f16 weight planes + reset barrier ===============
__global__ void prep_kernel(const float* __restrict__ Uf,
                            const float* __restrict__ Uiuo,
                            const float* __restrict__ Ww) {
    if (blockIdx.x == 0 && threadIdx.x == 0) { g_cnt = 0u; g_gen = 0u; }
    int idx0 = blockIdx.x * 256 + threadIdx.x;
    for (int idx = idx0; idx < 16384; idx += 2048) {
        if (idx < 6144) {                 // U_iuo f16 plane [192n][64k]
            int n = idx >> 5, kp = idx & 31;
            uint32_t off = SW128((uint32_t)(n * 128 + kp * 4)) >> 2;
            g_Wpl[off] = h2pk(Uiuo[(2 * kp) * 192 + n], Uiuo[(2 * kp + 1) * 192 + n]);
        } else if (idx < 8192) {          // U_f f16 plane (x0.5) [64n][64k]
            int i = idx - 6144;
            int n = i >> 5, kp = i & 31;
            uint32_t off = SW128((uint32_t)(n * 128 + kp * 4)) >> 2;
            g_Wpl[6144 + off] = h2pk(0.5f * Uf[(2 * kp) * 64 + n],
                                     0.5f * Uf[(2 * kp + 1) * 64 + n]);
        } else {                          // W_w f16 plane [256n][64k]
            int i = idx - 8192;
            int n = i >> 5, kp = i & 31;
            uint32_t off = SW128((uint32_t)(n * 128 + kp * 4)) >> 2;
            g_Wpl[8192 + off] = h2pk(Ww[(2 * kp) * 256 + n],
                                     Ww[(2 * kp + 1) * 256 + n]);
        }
    }
}

// ========== single persistent kernel: Wx + gather + LSTM, all 6 depths ===========
#define UA_F 0
#define UF_F 24576
#define WW_F 32768
#define XE_F 65536         // embeddings f16 [64r][64k] swizzled
#define AS_F 73728         // hs / new_h f16 staging
#define FS_F 81920         // f-gate: 0.5*(Wx_f + b_f), [64r][33 u32] padded
#define BF_F 90368         // branch_f f16, [64r][33 u32] padded
#define LB_F 98816         // 64 labels
#define NODE_SMEM 99072
#define NODE_GRID 256

__global__ __launch_bounds__(256, 2) void node_all_kernel(const int* __restrict__ labels,
                                                          const int* __restrict__ child_idx,
                                                          const float* __restrict__ E,
                                                          const float* __restrict__ Wb,
                                                          float* __restrict__ out) {
    extern __shared__ char smc[];
    const uint32_t sb = smem_u32(smc);
    const int tid = threadIdx.x, lane = tid & 31, w = tid >> 5;

    const unsigned gen0 = *((volatile unsigned*)&g_gen);

    // stage all f16 weight planes ONCE per CTA (persist across depths)
    for (int i = tid; i < 4096; i += 256)
        reinterpret_cast<uint4*>(smc)[i] = __ldg(reinterpret_cast<const uint4*>(g_Wpl) + i);
    __syncthreads();

    uint32_t* FS32 = reinterpret_cast<uint32_t*>(smc + FS_F);
    uint32_t* BF32 = reinterpret_cast<uint32_t*>(smc + BF_F);
    int* LBi = reinterpret_cast<int*>(smc + LB_F);
    const unsigned FULL = 0xffffffffu;
    const int g = lane >> 2, q = lane & 3;
    const int mrow = 16 * (w & 3), cg = w >> 2;
    const int lrow = ((lane >> 3) & 1) * 8 + (lane & 7);
    const int lkb  = (lane >> 4) * 16;

    for (int depth = 0; depth < D_; depth++) {
        const int rb = depth & 1;
        const u64* __restrict__ sp = g_st[rb];
        u64* __restrict__ sn = g_st[rb ^ 1];
        const size_t dN = (size_t)depth * N_;
        const bool last = (depth == D_ - 1);

        for (int ts = 0; ts < 2; ts++) {
            if (ts) __syncthreads();   // full reuse hazard across tiles
            const int nb = (blockIdx.x * 2 + ts) * 64;

            // ========== phase 0a: labels + embeddings -> XE (f16 swizzled) ==========
            if (tid < 64) LBi[tid] = labels[dN + nb + tid];
            __syncthreads();
#pragma unroll
            for (int i = 0; i < 4; i++) {
                int linear = i * 256 + tid;
                int r = linear >> 4, f = linear & 15;
                float4 v = __ldg(reinterpret_cast<const float4*>(
                                     E + (size_t)LBi[r] * DIN_) + f);
                u64 pk = ((u64)h2pk(v.z, v.w) << 32) | h2pk(v.x, v.y);
                *reinterpret_cast<u64*>(smc + XE_F + SW128((uint32_t)(r * 128 + f * 8)))
                    = pk;
            }
            __syncthreads();

            // ========== phase 0b: f-block Wx = E @ Wf + b_f (pre-halved -> FS) ======
            if (depth != 0) {
                float af[4][4];
#pragma unroll
                for (int j4 = 0; j4 < 4; j4++)
#pragma unroll
                    for (int e = 0; e < 4; e++) af[j4][e] = 0.f;
#pragma unroll
                for (int kc = 0; kc < 4; kc++) {
                    const int koff = kc * 32 + lkb;
                    uint32_t a[4];
                    ldm_x4(a, sb + XE_F + SW128((uint32_t)((mrow + lrow) * 128 + koff)));
#pragma unroll
                    for (int tp = 0; tp < 2; tp++) {
                        int nrow = cg * 32 + tp * 16 + lrow;   // WW rows 0..63 = f
                        uint32_t bb[4];
                        ldm_x4(bb, sb + WW_F + SW128((uint32_t)(nrow * 128 + koff)));
                        mma16816h(af[2 * tp],     a, bb[0], bb[2]);
                        mma16816h(af[2 * tp + 1], a, bb[1], bb[3]);
                    }
                }
#pragma unroll
                for (int j4 = 0; j4 < 4; j4++) {
                    const int dp = 16 * cg + 4 * j4 + q;
                    float2 bia = __ldg(reinterpret_cast<const float2*>(Wb + 2 * dp));
#pragma unroll
                    for (int rh = 0; rh < 2; rh++) {
                        const int r = mrow + 8 * rh + g;
                        FS32[r * 33 + dp] = h2pk(0.5f * (af[j4][2 * rh] + bia.x),
                                                 0.5f * (af[j4][2 * rh + 1] + bia.y));
                    }
                }
                __syncthreads();   // FS ready for gather

                // ========== phase 1: gather children (LDG.128 per child) ============
#pragma unroll
                for (int iter = 0; iter < 2; iter++) {
                    const int n0 = nb + 32 * iter + 4 * w;
                    const int rl0 = 32 * iter + 4 * w;
                    int ci0 = child_idx[(dN + n0) * K_ + lane];
                    int ci1 = child_idx[(dN + n0) * K_ + 32 + lane];
                    u64 wfh[4], hs[4] = {0, 0, 0, 0}, bfa[4] = {0, 0, 0, 0};
#pragma unroll
                    for (int q4 = 0; q4 < 4; q4++)
                        wfh[q4] = h2up(FS32[(rl0 + q4) * 33 + lane]);
#pragma unroll 4
                    for (int k = 0; k < K_; k++) {
#pragma unroll
                        for (int q4 = 0; q4 < 4; q4++) {
                            int sl = q4 * 16 + k;
                            int c = (sl < 32) ? __shfl_sync(FULL, ci0, sl)
                                              : __shfl_sync(FULL, ci1, sl - 32);
                            ulonglong2 s = __ldg(reinterpret_cast<const ulonglong2*>(
                                                     sp + 2 * (c * 32 + lane)));
                            hs[q4] = add2_(hs[q4], h2up((uint32_t)s.y));
                            bfa[q4] = fma2_(s.x,
                                            sig2h(add2_(wfh[q4],
                                                        h2up((uint32_t)(s.y >> 32)))),
                                            bfa[q4]);
                        }
                    }
#pragma unroll
                    for (int q4 = 0; q4 < 4; q4++) {
                        int r = rl0 + q4;
                        float xl, xh; upk2(hs[q4], xl, xh);
                        *reinterpret_cast<uint32_t*>(
                            smc + AS_F + SW128((uint32_t)(r * 128 + 4 * lane)))
                            = h2pk(xl, xh);
                        float bl, bh; upk2(bfa[q4], bl, bh);
                        BF32[r * 33 + lane] = h2pk(bl, bh);
                    }
                }
                __syncthreads();
            }

            // ========== phase 2: iuo = E@W_iuo (+ hs@U_iuo if depth>0) =============
            float acc[3][4][4];
#pragma unroll
            for (int b = 0; b < 3; b++)
#pragma unroll
                for (int j4 = 0; j4 < 4; j4++)
#pragma unroll
                    for (int e = 0; e < 4; e++) acc[b][j4][e] = 0.f;

#pragma unroll
            for (int kc = 0; kc < 4; kc++) {
                const int koff = kc * 32 + lkb;
                uint32_t a[4];
                ldm_x4(a, sb + XE_F + SW128((uint32_t)((mrow + lrow) * 128 + koff)));
#pragma unroll
                for (int b = 0; b < 3; b++)
#pragma unroll
                    for (int tp = 0; tp < 2; tp++) {
                        int nrow = (b + 1) * 64 + cg * 32 + tp * 16 + lrow;
                        uint32_t bb[4];
                        ldm_x4(bb, sb + WW_F + SW128((uint32_t)(nrow * 128 + koff)));
                        mma16816h(acc[b][2 * tp],     a, bb[0], bb[2]);
                        mma16816h(acc[b][2 * tp + 1], a, bb[1], bb[3]);
                    }
            }
            if (depth != 0) {
#pragma unroll
                for (int kc = 0; kc < 4; kc++) {
                    const int koff = kc * 32 + lkb;
                    uint32_t a[4];
                    ldm_x4(a, sb + AS_F + SW128((uint32_t)((mrow + lrow) * 128 + koff)));
#pragma unroll
                    for (int b = 0; b < 3; b++)
#pragma unroll
                        for (int tp = 0; tp < 2; tp++) {
                            int nrow = b * 64 + cg * 32 + tp * 16 + lrow;
                            uint32_t bb[4];
                            ldm_x4(bb, sb + UA_F + SW128((uint32_t)(nrow * 128 + koff)));
                            mma16816h(acc[b][2 * tp],     a, bb[0], bb[2]);
                            mma16816h(acc[b][2 * tp + 1], a, bb[1], bb[3]);
                        }
                }
            }

            // ========== phase 3: gates (bias from Wb, row-invariant) ===============
            u64 nhv[4][2];
#pragma unroll
            for (int j4 = 0; j4 < 4; j4++) {
                const int dp = 16 * cg + 4 * j4 + q;
                float2 bi = __ldg(reinterpret_cast<const float2*>(Wb + 64 + 2 * dp));
                float2 bu = __ldg(reinterpret_cast<const float2*>(Wb + 128 + 2 * dp));
                float2 bo = __ldg(reinterpret_cast<const float2*>(Wb + 192 + 2 * dp));
                u64 bi2 = pk2(bi.x, bi.y), bu2 = pk2(bu.x, bu.y), bo2 = pk2(bo.x, bo.y);
#pragma unroll
                for (int rh = 0; rh < 2; rh++) {
                    const int r = mrow + 8 * rh + g;
                    u64 ai = pk2(acc[0][j4][2 * rh], acc[0][j4][2 * rh + 1]);
                    u64 au = pk2(acc[1][j4][2 * rh], acc[1][j4][2 * rh + 1]);
                    u64 ao = pk2(acc[2][j4][2 * rh], acc[2][j4][2 * rh + 1]);
                    u64 ig = sig2h(mul2_(add2_(ai, bi2), HALF2));
                    u64 ug = tanh2(add2_(au, bu2));
                    u64 og = sig2h(mul2_(add2_(ao, bo2), HALF2));
                    u64 bfv = (depth != 0) ? h2up(BF32[r * 33 + dp]) : 0ULL;
                    u64 ncv = fma2_(ig, ug, bfv);
                    u64 nh = mul2_(og, tanh2(ncv));
                    nhv[j4][rh] = nh;
                    if (last) {
                        reinterpret_cast<u64*>(out)[(size_t)(nb + r) * 32 + dp] = nh;
                    } else {
                        sn[2 * ((size_t)(nb + r + 1) * 32 + dp)] = ncv;   // c word
                    }
                }
            }

            if (!last) {
                // ========== phase 4: stage new_h, G = 0.5*(new_h @ U_f) =============
                __syncthreads();
#pragma unroll
                for (int j4 = 0; j4 < 4; j4++) {
                    const int dp = 16 * cg + 4 * j4 + q;
#pragma unroll
                    for (int rh = 0; rh < 2; rh++) {
                        const int r = mrow + 8 * rh + g;
                        float xl, xh; upk2(nhv[j4][rh], xl, xh);
                        *reinterpret_cast<uint32_t*>(
                            smc + AS_F + SW128((uint32_t)(r * 128 + 4 * dp)))
                            = h2pk(xl, xh);
                    }
                }
                __syncthreads();

                float ga[4][4];
#pragma unroll
                for (int t2 = 0; t2 < 4; t2++)
#pragma unroll
                    for (int e = 0; e < 4; e++) ga[t2][e] = 0.f;

#pragma unroll
                for (int kc = 0; kc < 4; kc++) {
                    const int koff = kc * 32 + lkb;
                    uint32_t a[4];
                    ldm_x4(a, sb + AS_F + SW128((uint32_t)((mrow + lrow) * 128 + koff)));
#pragma unroll
                    for (int tp = 0; tp < 2; tp++) {
                        int nrow = cg * 32 + tp * 16 + lrow;
                        uint32_t bb[4];
                        ldm_x4(bb, sb + UF_F + SW128((uint32_t)(nrow * 128 + koff)));
                        mma16816h(ga[2 * tp],     a, bb[0], bb[2]);
                        mma16816h(ga[2 * tp + 1], a, bb[1], bb[3]);
                    }
                }
#pragma unroll
                for (int tg = 0; tg < 4; tg++) {
                    const int dp = 16 * cg + 4 * tg + q;
#pragma unroll
                    for (int rh = 0; rh < 2; rh++) {
                        const int r = mrow + 8 * rh + g;
                        float xl, xh; upk2(nhv[tg][rh], xl, xh);
                        uint32_t hu = h2pk(xl, xh);
                        uint32_t gu = h2pk(ga[tg][2 * rh], ga[tg][2 * rh + 1]);
                        sn[2 * ((size_t)(nb + r + 1) * 32 + dp) + 1] =
                            ((u64)gu << 32) | hu;                       // hG word
                    }
                }
            }
        }

        // ================= grid barrier between depths =================
        if (!last) {
            __syncthreads();
            if (tid == 0) {
                __threadfence();
                unsigned a = atomicAdd(&g_cnt, 1u);
                unsigned target = gen0 + (unsigned)depth + 1u;
                if ((a % NODE_GRID) == NODE_GRID - 1) {
                    atomicAdd(&g_gen, 1u);
                } else {
                    while (*((volatile unsigned*)&g_gen) < target) {}
                }
                __threadfence();
            }
            __syncthreads();
        }
    }
}

extern "C" void kernel_launch(void* const* d_in, const int* in_sizes, int n_in,
                              void* d_out, int out_size) {
    const int*   labels    = (const int*)d_in[0];
    const int*   child_idx = (const int*)d_in[1];
    const float* E         = (const float*)d_in[2];
    const float* Ww        = (const float*)d_in[3];
    const float* Wb        = (const float*)d_in[4];
    const float* Uf        = (const float*)d_in[5];
    const float* Uiuo      = (const float*)d_in[6];
    float*       out       = (float*)d_out;

    cudaFuncSetAttribute(node_all_kernel, cudaFuncAttributeMaxDynamicSharedMemorySize,
                         NODE_SMEM);

    prep_kernel<<<8, 256>>>(Uf, Uiuo, Ww);
    node_all_kernel<<<NODE_GRID, 256, NODE_SMEM>>>(labels, child_idx, E, Wb, out);
}

// round 16
// speedup vs baseline: 1.8694x; 1.0436x over previous
#include <cuda_runtime.h>
#include <cuda_bf16.h>
#include <cuda_fp16.h>
#include <cstdint>

#define D_ 6
#define N_ 32768
#define K_ 16
#define DIN_ 64
#define DOUT_ 64
#define V_ 100000

typedef unsigned long long u64;

// Interleaved ping-pong state, 16B per (row, dim-pair):
//   word0 (u64): c as f32x2
//   word1 (u64): low u32 = h as f16x2, high u32 = G(=0.5*h@Uf) as f16x2
// Row 0 = zero row for masked children: .bss zero, never written.
__device__ u64 g_st[2][(N_ + 1) * 64];
// Pre-swizzled f16 weight planes: UA[6144] | UF[2048] | WW[8192]  (u32 words)
__device__ uint32_t g_Wpl[16384];
// E pre-converted to f16x2: [V][32 u32]
__device__ uint32_t g_Ef16[(size_t)V_ * 32];
// software grid barrier
__device__ unsigned g_cnt;
__device__ unsigned g_gen;

#define HALF2 0x3F0000003F000000ULL   // {0.5f, 0.5f} f32x2
#define HHALF2 0x38003800u            // {0.5, 0.5} f16x2

__device__ __forceinline__ u64 pk2(float lo, float hi) {
    u64 r; asm("mov.b64 %0, {%1,%2};" : "=l"(r) : "f"(lo), "f"(hi)); return r;
}
__device__ __forceinline__ void upk2(u64 v, float& lo, float& hi) {
    asm("mov.b64 {%0,%1}, %2;" : "=f"(lo), "=f"(hi) : "l"(v));
}
__device__ __forceinline__ u64 fma2_(u64 a, u64 b, u64 c) {
    u64 d; asm("fma.rn.f32x2 %0, %1, %2, %3;" : "=l"(d) : "l"(a), "l"(b), "l"(c)); return d;
}
__device__ __forceinline__ u64 add2_(u64 a, u64 b) {
    u64 d; asm("add.rn.f32x2 %0, %1, %2;" : "=l"(d) : "l"(a), "l"(b)); return d;
}
__device__ __forceinline__ u64 mul2_(u64 a, u64 b) {
    u64 d; asm("mul.rn.f32x2 %0, %1, %2;" : "=l"(d) : "l"(a), "l"(b)); return d;
}
__device__ __forceinline__ float tanha(float x) {
    float y; asm("tanh.approx.f32 %0, %1;" : "=f"(y) : "f"(x)); return y;
}
__device__ __forceinline__ u64 sig2h(u64 argHalf) {   // sigmoid(2*arg), f32 path (gates)
    float a, b; upk2(argHalf, a, b);
    return fma2_(pk2(tanha(a), tanha(b)), HALF2, HALF2);
}
__device__ __forceinline__ u64 tanh2(u64 v) {
    float a, b; upk2(v, a, b);
    return pk2(tanha(a), tanha(b));
}
// f16x2 ops for the per-child forget gate
__device__ __forceinline__ uint32_t hadd2_(uint32_t a, uint32_t b) {
    uint32_t d; asm("add.f16x2 %0, %1, %2;" : "=r"(d) : "r"(a), "r"(b)); return d;
}
__device__ __forceinline__ uint32_t htanh2(uint32_t a) {
    uint32_t d; asm("tanh.approx.f16x2 %0, %1;" : "=r"(d) : "r"(a)); return d;
}
__device__ __forceinline__ uint32_t hfma2h(uint32_t a, uint32_t b, uint32_t c) {
    uint32_t d; asm("fma.rn.f16x2 %0, %1, %2, %3;" : "=r"(d) : "r"(a), "r"(b), "r"(c)); return d;
}
__device__ __forceinline__ uint32_t smem_u32(const void* p) {
    uint32_t a;
    asm("{ .reg .u64 t; cvta.to.shared.u64 t, %1; cvt.u32.u64 %0, t; }" : "=r"(a) : "l"(p));
    return a;
}
__device__ __forceinline__ uint32_t h2pk(float lo, float hi) {
    __half2 h = __float22half2_rn(make_float2(lo, hi));
    return *reinterpret_cast<uint32_t*>(&h);
}
__device__ __forceinline__ u64 h2up(uint32_t v) {   // f16x2 -> f32x2 (u64)
    __half2 h = *reinterpret_cast<__half2*>(&v);
    float2 f = __half22float2(h);
    return pk2(f.x, f.y);
}
#define SW128(off) ((off) ^ (((off) >> 3) & 0x70))

__device__ __forceinline__ void ldm_x4(uint32_t* r, uint32_t addr) {
    asm volatile("ldmatrix.sync.aligned.m8n8.x4.shared.b16 {%0,%1,%2,%3}, [%4];"
                 : "=r"(r[0]), "=r"(r[1]), "=r"(r[2]), "=r"(r[3]) : "r"(addr));
}
__device__ __forceinline__ void mma16816h(float* c, const uint32_t* a,
                                          uint32_t b0, uint32_t b1) {
    asm volatile(
        "mma.sync.aligned.m16n8k16.row.col.f32.f16.f16.f32 "
        "{%0,%1,%2,%3}, {%4,%5,%6,%7}, {%8,%9}, {%0,%1,%2,%3};"
        : "+f"(c[0]), "+f"(c[1]), "+f"(c[2]), "+f"(c[3])
        : "r"(a[0]), "r"(a[1]), "r"(a[2]), "r"(a[3]), "r"(b0), "r"(b1));
}

// ============ prep: weight planes, E->f16, barrier reset ========================
__global__ void prep_kernel(const float* __restrict__ Uf,
                            const float* __restrict__ Uiuo,
                            const float* __restrict__ Ww,
                            const float* __restrict__ E) {
    if (blockIdx.x == 0 && threadIdx.x == 0) { g_cnt = 0u; g_gen = 0u; }
    const int gid = blockIdx.x * 256 + threadIdx.x;
    // E conversion: 3.2M u32 outputs across all 65536 threads
    for (int i = gid; i < V_ * 32; i += 256 * 256) {
        float2 v = __ldg(reinterpret_cast<const float2*>(E) + i);
        g_Ef16[i] = h2pk(v.x, v.y);
    }
    // weight planes: blocks 0-7 only
    if (blockIdx.x < 8) {
        int idx0 = blockIdx.x * 256 + threadIdx.x;
        for (int idx = idx0; idx < 16384; idx += 2048) {
            if (idx < 6144) {                 // U_iuo f16 plane [192n][64k]
                int n = idx >> 5, kp = idx & 31;
                uint32_t off = SW128((uint32_t)(n * 128 + kp * 4)) >> 2;
                g_Wpl[off] = h2pk(Uiuo[(2 * kp) * 192 + n],
                                  Uiuo[(2 * kp + 1) * 192 + n]);
            } else if (idx < 8192) {          // U_f f16 plane (x0.5) [64n][64k]
                int i2 = idx - 6144;
                int n = i2 >> 5, kp = i2 & 31;
                uint32_t off = SW128((uint32_t)(n * 128 + kp * 4)) >> 2;
                g_Wpl[6144 + off] = h2pk(0.5f * Uf[(2 * kp) * 64 + n],
                                         0.5f * Uf[(2 * kp + 1) * 64 + n]);
            } else {                          // W_w f16 plane [256n][64k]
                int i2 = idx - 8192;
                int n = i2 >> 5, kp = i2 & 31;
                uint32_t off = SW128((uint32_t)(n * 128 + kp * 4)) >> 2;
                g_Wpl[8192 + off] = h2pk(Ww[(2 * kp) * 256 + n],
                                         Ww[(2 * kp + 1) * 256 + n]);
            }
        }
    }
}

// ========== single persistent kernel: Wx + gather + LSTM, all 6 depths ===========
#define UA_F 0
#define UF_F 24576
#define WW_F 32768
#define XE_F 65536         // embeddings f16 [64r][64k] swizzled
#define AS_F 73728         // hs / new_h f16 staging
#define FS_F 81920         // f-gate: 0.5*(Wx_f + b_f) f16x2, [64r][33 u32] padded
#define BF_F 90368         // branch_f f16, [64r][33 u32] padded
#define LB_F 98816         // 64 labels
#define NODE_SMEM 99072
#define NODE_GRID 256

__global__ __launch_bounds__(256, 2) void node_all_kernel(const int* __restrict__ labels,
                                                          const int* __restrict__ child_idx,
                                                          const float* __restrict__ Wb,
                                                          float* __restrict__ out) {
    extern __shared__ char smc[];
    const uint32_t sb = smem_u32(smc);
    const int tid = threadIdx.x, lane = tid & 31, w = tid >> 5;

    const unsigned gen0 = *((volatile unsigned*)&g_gen);

    // stage all f16 weight planes ONCE per CTA (persist across depths)
    for (int i = tid; i < 4096; i += 256)
        reinterpret_cast<uint4*>(smc)[i] = __ldg(reinterpret_cast<const uint4*>(g_Wpl) + i);
    __syncthreads();

    uint32_t* FS32 = reinterpret_cast<uint32_t*>(smc + FS_F);
    uint32_t* BF32 = reinterpret_cast<uint32_t*>(smc + BF_F);
    int* LBi = reinterpret_cast<int*>(smc + LB_F);
    const int g = lane >> 2, q = lane & 3;
    const int mrow = 16 * (w & 3), cg = w >> 2;
    const int lrow = ((lane >> 3) & 1) * 8 + (lane & 7);
    const int lkb  = (lane >> 4) * 16;

    for (int depth = 0; depth < D_; depth++) {
        const int rb = depth & 1;
        const u64* __restrict__ sp = g_st[rb];
        u64* __restrict__ sn = g_st[rb ^ 1];
        const size_t dN = (size_t)depth * N_;
        const bool last = (depth == D_ - 1);

        for (int ts = 0; ts < 2; ts++) {
            if (ts) __syncthreads();   // full reuse hazard across tiles
            const int nb = (blockIdx.x * 2 + ts) * 64;

            // ---- prefetch child indices for both gather iterations (hide latency)
            int ciA0 = 0, ciA1 = 0, ciB0 = 0, ciB1 = 0;
            if (depth != 0) {
                const size_t cA = (dN + nb + 4 * w) * K_;
                const size_t cB = (dN + nb + 32 + 4 * w) * K_;
                ciA0 = child_idx[cA + lane];
                ciA1 = child_idx[cA + 32 + lane];
                ciB0 = child_idx[cB + lane];
                ciB1 = child_idx[cB + 32 + lane];
            }

            // ========== phase 0a: labels + f16 embeddings -> XE ====================
            if (tid < 64) LBi[tid] = labels[dN + nb + tid];
            __syncthreads();
#pragma unroll
            for (int i = 0; i < 2; i++) {
                int linear = i * 256 + tid;       // 512 x 16B chunks
                int r = linear >> 3, f = linear & 7;
                uint4 v = __ldg(reinterpret_cast<const uint4*>(
                                    g_Ef16 + (size_t)LBi[r] * 32) + f);
                *reinterpret_cast<uint4*>(smc + XE_F +
                                          SW128((uint32_t)(r * 128 + f * 16))) = v;
            }
            __syncthreads();

            // ========== phase 0b: f-block Wx = E @ Wf + b_f (pre-halved -> FS) ======
            if (depth != 0) {
                float af[4][4];
#pragma unroll
                for (int j4 = 0; j4 < 4; j4++)
#pragma unroll
                    for (int e = 0; e < 4; e++) af[j4][e] = 0.f;
#pragma unroll
                for (int kc = 0; kc < 4; kc++) {
                    const int koff = kc * 32 + lkb;
                    uint32_t a[4];
                    ldm_x4(a, sb + XE_F + SW128((uint32_t)((mrow + lrow) * 128 + koff)));
#pragma unroll
                    for (int tp = 0; tp < 2; tp++) {
                        int nrow = cg * 32 + tp * 16 + lrow;   // WW rows 0..63 = f
                        uint32_t bb[4];
                        ldm_x4(bb, sb + WW_F + SW128((uint32_t)(nrow * 128 + koff)));
                        mma16816h(af[2 * tp],     a, bb[0], bb[2]);
                        mma16816h(af[2 * tp + 1], a, bb[1], bb[3]);
                    }
                }
#pragma unroll
                for (int j4 = 0; j4 < 4; j4++) {
                    const int dp = 16 * cg + 4 * j4 + q;
                    float2 bia = __ldg(reinterpret_cast<const float2*>(Wb + 2 * dp));
#pragma unroll
                    for (int rh = 0; rh < 2; rh++) {
                        const int r = mrow + 8 * rh + g;
                        FS32[r * 33 + dp] = h2pk(0.5f * (af[j4][2 * rh] + bia.x),
                                                 0.5f * (af[j4][2 * rh + 1] + bia.y));
                    }
                }
                __syncthreads();   // FS ready for gather

                // ========== phase 1: gather children, f-gate in f16x2 ===============
#pragma unroll
                for (int iter = 0; iter < 2; iter++) {
                    const int rl0 = 32 * iter + 4 * w;
                    int ci0 = iter ? ciB0 : ciA0;
                    int ci1 = iter ? ciB1 : ciA1;
                    uint32_t wf16[4];
                    u64 hs[4] = {0, 0, 0, 0}, bfa[4] = {0, 0, 0, 0};
#pragma unroll
                    for (int q4 = 0; q4 < 4; q4++)
                        wf16[q4] = FS32[(rl0 + q4) * 33 + lane];
#pragma unroll 4
                    for (int k = 0; k < K_; k++) {
#pragma unroll
                        for (int q4 = 0; q4 < 4; q4++) {
                            int sl = q4 * 16 + k;
                            int c = (sl < 32) ? __shfl_sync(0xffffffffu, ci0, sl)
                                              : __shfl_sync(0xffffffffu, ci1, sl - 32);
                            ulonglong2 s = __ldg(reinterpret_cast<const ulonglong2*>(
                                                     sp + 2 * (c * 32 + lane)));
                            uint32_t Gh = (uint32_t)(s.y >> 32);
                            uint32_t sg = hfma2h(htanh2(hadd2_(wf16[q4], Gh)),
                                                 HHALF2, HHALF2);
                            hs[q4] = add2_(hs[q4], h2up((uint32_t)s.y));
                            bfa[q4] = fma2_(s.x, h2up(sg), bfa[q4]);
                        }
                    }
#pragma unroll
                    for (int q4 = 0; q4 < 4; q4++) {
                        int r = rl0 + q4;
                        float xl, xh; upk2(hs[q4], xl, xh);
                        *reinterpret_cast<uint32_t*>(
                            smc + AS_F + SW128((uint32_t)(r * 128 + 4 * lane)))
                            = h2pk(xl, xh);
                        float bl, bh; upk2(bfa[q4], bl, bh);
                        BF32[r * 33 + lane] = h2pk(bl, bh);
                    }
                }
                __syncthreads();
            }

            // ========== phase 2: iuo = E@W_iuo (+ hs@U_iuo if depth>0) =============
            float acc[3][4][4];
#pragma unroll
            for (int b = 0; b < 3; b++)
#pragma unroll
                for (int j4 = 0; j4 < 4; j4++)
#pragma unroll
                    for (int e = 0; e < 4; e++) acc[b][j4][e] = 0.f;

#pragma unroll
            for (int kc = 0; kc < 4; kc++) {
                const int koff = kc * 32 + lkb;
                uint32_t a[4];
                ldm_x4(a, sb + XE_F + SW128((uint32_t)((mrow + lrow) * 128 + koff)));
#pragma unroll
                for (int b = 0; b < 3; b++)
#pragma unroll
                    for (int tp = 0; tp < 2; tp++) {
                        int nrow = (b + 1) * 64 + cg * 32 + tp * 16 + lrow;
                        uint32_t bb[4];
                        ldm_x4(bb, sb + WW_F + SW128((uint32_t)(nrow * 128 + koff)));
                        mma16816h(acc[b][2 * tp],     a, bb[0], bb[2]);
                        mma16816h(acc[b][2 * tp + 1], a, bb[1], bb[3]);
                    }
            }
            if (depth != 0) {
#pragma unroll
                for (int kc = 0; kc < 4; kc++) {
                    const int koff = kc * 32 + lkb;
                    uint32_t a[4];
                    ldm_x4(a, sb + AS_F + SW128((uint32_t)((mrow + lrow) * 128 + koff)));
#pragma unroll
                    for (int b = 0; b < 3; b++)
#pragma unroll
                        for (int tp = 0; tp < 2; tp++) {
                            int nrow = b * 64 + cg * 32 + tp * 16 + lrow;
                            uint32_t bb[4];
                            ldm_x4(bb, sb + UA_F + SW128((uint32_t)(nrow * 128 + koff)));
                            mma16816h(acc[b][2 * tp],     a, bb[0], bb[2]);
                            mma16816h(acc[b][2 * tp + 1], a, bb[1], bb[3]);
                        }
                }
            }

            // ========== phase 3: gates ==============================================
            u64 nhv[4][2], ncvv[4][2];
#pragma unroll
            for (int j4 = 0; j4 < 4; j4++) {
                const int dp = 16 * cg + 4 * j4 + q;
                float2 bi = __ldg(reinterpret_cast<const float2*>(Wb + 64 + 2 * dp));
                float2 bu = __ldg(reinterpret_cast<const float2*>(Wb + 128 + 2 * dp));
                float2 bo = __ldg(reinterpret_cast<const float2*>(Wb + 192 + 2 * dp));
                u64 bi2 = pk2(bi.x, bi.y), bu2 = pk2(bu.x, bu.y), bo2 = pk2(bo.x, bo.y);
#pragma unroll
                for (int rh = 0; rh < 2; rh++) {
                    const int r = mrow + 8 * rh + g;
                    u64 ai = pk2(acc[0][j4][2 * rh], acc[0][j4][2 * rh + 1]);
                    u64 au = pk2(acc[1][j4][2 * rh], acc[1][j4][2 * rh + 1]);
                    u64 ao = pk2(acc[2][j4][2 * rh], acc[2][j4][2 * rh + 1]);
                    u64 ig = sig2h(mul2_(add2_(ai, bi2), HALF2));
                    u64 ug = tanh2(add2_(au, bu2));
                    u64 og = sig2h(mul2_(add2_(ao, bo2), HALF2));
                    u64 bfv = (depth != 0) ? h2up(BF32[r * 33 + dp]) : 0ULL;
                    u64 ncv = fma2_(ig, ug, bfv);
                    u64 nh = mul2_(og, tanh2(ncv));
                    nhv[j4][rh] = nh;
                    ncvv[j4][rh] = ncv;
                    if (last)
                        reinterpret_cast<u64*>(out)[(size_t)(nb + r) * 32 + dp] = nh;
                }
            }

            if (!last) {
                // ========== phase 4: stage new_h, G = 0.5*(new_h @ U_f) =============
                __syncthreads();
#pragma unroll
                for (int j4 = 0; j4 < 4; j4++) {
                    const int dp = 16 * cg + 4 * j4 + q;
#pragma unroll
                    for (int rh = 0; rh < 2; rh++) {
                        const int r = mrow + 8 * rh + g;
                        float xl, xh; upk2(nhv[j4][rh], xl, xh);
                        *reinterpret_cast<uint32_t*>(
                            smc + AS_F + SW128((uint32_t)(r * 128 + 4 * dp)))
                            = h2pk(xl, xh);
                    }
                }
                __syncthreads();

                float ga[4][4];
#pragma unroll
                for (int t2 = 0; t2 < 4; t2++)
#pragma unroll
                    for (int e = 0; e < 4; e++) ga[t2][e] = 0.f;

#pragma unroll
                for (int kc = 0; kc < 4; kc++) {
                    const int koff = kc * 32 + lkb;
                    uint32_t a[4];
                    ldm_x4(a, sb + AS_F + SW128((uint32_t)((mrow + lrow) * 128 + koff)));
#pragma unroll
                    for (int tp = 0; tp < 2; tp++) {
                        int nrow = cg * 32 + tp * 16 + lrow;
                        uint32_t bb[4];
                        ldm_x4(bb, sb + UF_F + SW128((uint32_t)(nrow * 128 + koff)));
                        mma16816h(ga[2 * tp],     a, bb[0], bb[2]);
                        mma16816h(ga[2 * tp + 1], a, bb[1], bb[3]);
                    }
                }
                // combined STG.128 state store: {c f32x2, h|G f16x2}
#pragma unroll
                for (int tg = 0; tg < 4; tg++) {
                    const int dp = 16 * cg + 4 * tg + q;
#pragma unroll
                    for (int rh = 0; rh < 2; rh++) {
                        const int r = mrow + 8 * rh + g;
                        float xl, xh; upk2(nhv[tg][rh], xl, xh);
                        uint32_t hu = h2pk(xl, xh);
                        uint32_t gu = h2pk(ga[tg][2 * rh], ga[tg][2 * rh + 1]);
                        reinterpret_cast<ulonglong2*>(sn)[(size_t)(nb + r + 1) * 32 + dp]
                            = make_ulonglong2(ncvv[tg][rh], ((u64)gu << 32) | hu);
                    }
                }
            }
        }

        // ================= grid barrier between depths =================
        if (!last) {
            __syncthreads();
            if (tid == 0) {
                __threadfence();
                unsigned a = atomicAdd(&g_cnt, 1u);
                unsigned target = gen0 + (unsigned)depth + 1u;
                if ((a % NODE_GRID) == NODE_GRID - 1) {
                    atomicAdd(&g_gen, 1u);
                } else {
                    while (*((volatile unsigned*)&g_gen) < target) {}
                }
                __threadfence();
            }
            __syncthreads();
        }
    }
}

extern "C" void kernel_launch(void* const* d_in, const int* in_sizes, int n_in,
                              void* d_out, int out_size) {
    const int*   labels    = (const int*)d_in[0];
    const int*   child_idx = (const int*)d_in[1];
    const float* E         = (const float*)d_in[2];
    const float* Ww        = (const float*)d_in[3];
    const float* Wb        = (const float*)d_in[4];
    const float* Uf        = (const float*)d_in[5];
    const float* Uiuo      = (const float*)d_in[6];
    float*       out       = (float*)d_out;

    cudaFuncSetAttribute(node_all_kernel, cudaFuncAttributeMaxDynamicSharedMemorySize,
                         NODE_SMEM);

    prep_kernel<<<256, 256>>>(Uf, Uiuo, Ww, E);
    node_all_kernel<<<NODE_GRID, 256, NODE_SMEM>>>(labels, child_idx, Wb, out);
}